// round 14
// baseline (speedup 1.0000x reference)
#include <cuda_runtime.h>

// BilinearInterpolation: projective warp + bilinear sample.
// X: (16, 384, 384, 64) fp32 ; T: (16, 9) fp32 ; out: (16, 224, 224, 64) fp32.
//
// DRAM-bound at ~87% / ~6.9 TB/s on 745MB compulsory traffic. This round tests
// the last untried structure: a PERSISTENT grid-stride kernel (2368 CTAs =
// 148 SMs x 16 resident CTAs of 128 threads, single wave) replacing 100352
// one-shot CTAs (~42 waves), eliminating CTA launch/drain churn and wave
// transitions. Per-iteration mapping unchanged: one work item = one (batch,
// out-pixel, float4 channel group); 16 lanes/pixel -> fully contiguous 512B
// warp loads + stores.

#define OUT_H 224
#define OUT_W 224
#define HIN   384
#define WIN   384
#define CVEC  16   // 64 channels / 4 per float4

#define NSM        148
#define CTAS_PER_SM 16
#define THREADS    128
#define TOTAL_ITEMS (16 * OUT_H * OUT_W * CVEC)   // 12,845,056

__global__ __launch_bounds__(THREADS)
void bilerp_kernel(const float* __restrict__ X,
                   const float* __restrict__ T,
                   float* __restrict__ out)
{
    const int N = OUT_H * OUT_W;
    const int stride = gridDim.x * THREADS;

    for (int tid = blockIdx.x * THREADS + threadIdx.x;
         tid < TOTAL_ITEMS;
         tid += stride)
    {
        int g   = tid & (CVEC - 1);   // channel group within pixel
        int p   = tid >> 4;           // (b, pixel) flat index
        int b   = p / N;
        int pix = p - b * N;
        int oy  = pix / OUT_W;
        int ox  = pix - oy * OUT_W;

        // grid point in [-1,1]^2 (linspace with endpoints: step = 2/(dim-1))
        float gx = fmaf((float)ox, 2.0f / (float)(OUT_W - 1), -1.0f);
        float gy = fmaf((float)oy, 2.0f / (float)(OUT_H - 1), -1.0f);

        const float* Tb = T + b * 9;
        float t0 = __ldg(Tb + 0), t1 = __ldg(Tb + 1), t2 = __ldg(Tb + 2);
        float t3 = __ldg(Tb + 3), t4 = __ldg(Tb + 4), t5 = __ldg(Tb + 5);
        float t6 = __ldg(Tb + 6), t7 = __ldg(Tb + 7), t8 = __ldg(Tb + 8);

        float sx = fmaf(t0, gx, fmaf(t1, gy, t2));
        float sy = fmaf(t3, gx, fmaf(t4, gy, t5));
        float sz = fmaf(t6, gx, fmaf(t7, gy, t8)) + 1e-6f;

        float rz = 1.0f / sz;
        float x = 0.5f * fmaf(sx, rz, 1.0f) * (float)WIN;
        float y = 0.5f * fmaf(sy, rz, 1.0f) * (float)HIN;

        // truncation toward zero (matches astype(int32) / tf.cast)
        int x0 = (int)x;
        int y0 = (int)y;
        int x1 = x0 + 1;
        int y1 = y0 + 1;
        x0 = min(max(x0, 0), WIN - 1);
        x1 = min(max(x1, 0), WIN - 1);
        y0 = min(max(y0, 0), HIN - 1);
        y1 = min(max(y1, 0), HIN - 1);

        float x0f = (float)x0, x1f = (float)x1;
        float y0f = (float)y0, y1f = (float)y1;

        float wa = (x1f - x) * (y1f - y);
        float wb = (x1f - x) * (y - y0f);
        float wc = (x - x0f) * (y1f - y);
        float wd = (x - x0f) * (y - y0f);

        const float4* Xv = (const float4*)X;
        size_t bbase = (size_t)b * (HIN * WIN * CVEC);
        size_t r0 = bbase + (size_t)y0 * (WIN * CVEC);
        size_t r1 = bbase + (size_t)y1 * (WIN * CVEC);
        size_t ca = (size_t)x0 * CVEC + g;
        size_t cc = (size_t)x1 * CVEC + g;

        float4 pa = __ldg(Xv + r0 + ca);
        float4 pb = __ldg(Xv + r1 + ca);
        float4 pc = __ldg(Xv + r0 + cc);
        float4 pd = __ldg(Xv + r1 + cc);

        float4 o;
        o.x = wa * pa.x + wb * pb.x + wc * pc.x + wd * pd.x;
        o.y = wa * pa.y + wb * pb.y + wc * pc.y + wd * pd.y;
        o.z = wa * pa.z + wb * pb.z + wc * pc.z + wd * pd.z;
        o.w = wa * pa.w + wb * pb.w + wc * pc.w + wd * pd.w;

        ((float4*)out)[(size_t)p * CVEC + g] = o;
    }
}

extern "C" void kernel_launch(void* const* d_in, const int* in_sizes, int n_in,
                              void* d_out, int out_size)
{
    const float* X = (const float*)d_in[0];
    const float* T = (const float*)d_in[1];
    float* out = (float*)d_out;

    const int blocks = NSM * CTAS_PER_SM;  // 2368 CTAs: one resident wave
    bilerp_kernel<<<blocks, THREADS>>>(X, T, out);
}

// round 15
// speedup vs baseline: 1.0685x; 1.0685x over previous
#include <cuda_runtime.h>

// BilinearInterpolation: projective warp + bilinear sample.
// X: (16, 384, 384, 64) fp32 ; T: (16, 9) fp32 ; out: (16, 224, 224, 64) fp32.
//
// FINAL (verified over 6 identical runs: wall 110.7-111.3us, ncu 106.8-108.9us,
// DRAM 86.3-88.0%, ~6.9 TB/s). Pure HBM-bound at the structural roofline:
// 745MB traffic = 540MB reads (each touched input byte crosses HBM once; the
// one-shot block-ordered sweep keeps ~2-3 batch images L2-resident, absorbing
// all bilinear-corner/row reuse) + 205MB write-once output. Alternatives all
// measured worse: CTA 64/256/512, 2 groups/thread, __stcs stores, load
// reorders, and a persistent grid-stride kernel (118us - striding breaks the
// batch-sequential L2 locality). Config: 128-thread one-shot CTAs, one thread
// = one (batch, out-pixel, float4 channel group), 16 threads/pixel -> fully
// contiguous 512B warp loads and stores, default cache policies.

#define OUT_H 224
#define OUT_W 224
#define HIN   384
#define WIN   384
#define CVEC  16   // 64 channels / 4 per float4

__global__ __launch_bounds__(128)
void bilerp_kernel(const float* __restrict__ X,
                   const float* __restrict__ T,
                   float* __restrict__ out)
{
    int tid = blockIdx.x * blockDim.x + threadIdx.x;

    const int N = OUT_H * OUT_W;
    int g   = tid & (CVEC - 1);   // channel group within pixel
    int p   = tid >> 4;           // (b, pixel) flat index
    int b   = p / N;
    int pix = p - b * N;
    int oy  = pix / OUT_W;
    int ox  = pix - oy * OUT_W;

    // grid point in [-1,1]^2 (linspace with endpoints: step = 2/(dim-1))
    float gx = fmaf((float)ox, 2.0f / (float)(OUT_W - 1), -1.0f);
    float gy = fmaf((float)oy, 2.0f / (float)(OUT_H - 1), -1.0f);

    const float* Tb = T + b * 9;
    float t0 = __ldg(Tb + 0), t1 = __ldg(Tb + 1), t2 = __ldg(Tb + 2);
    float t3 = __ldg(Tb + 3), t4 = __ldg(Tb + 4), t5 = __ldg(Tb + 5);
    float t6 = __ldg(Tb + 6), t7 = __ldg(Tb + 7), t8 = __ldg(Tb + 8);

    float sx = fmaf(t0, gx, fmaf(t1, gy, t2));
    float sy = fmaf(t3, gx, fmaf(t4, gy, t5));
    float sz = fmaf(t6, gx, fmaf(t7, gy, t8)) + 1e-6f;

    float rz = 1.0f / sz;
    float x = 0.5f * fmaf(sx, rz, 1.0f) * (float)WIN;
    float y = 0.5f * fmaf(sy, rz, 1.0f) * (float)HIN;

    // truncation toward zero (matches astype(int32) / tf.cast)
    int x0 = (int)x;
    int y0 = (int)y;
    int x1 = x0 + 1;
    int y1 = y0 + 1;
    x0 = min(max(x0, 0), WIN - 1);
    x1 = min(max(x1, 0), WIN - 1);
    y0 = min(max(y0, 0), HIN - 1);
    y1 = min(max(y1, 0), HIN - 1);

    float x0f = (float)x0, x1f = (float)x1;
    float y0f = (float)y0, y1f = (float)y1;

    float wa = (x1f - x) * (y1f - y);
    float wb = (x1f - x) * (y - y0f);
    float wc = (x - x0f) * (y1f - y);
    float wd = (x - x0f) * (y - y0f);

    const float4* Xv = (const float4*)X;
    size_t bbase = (size_t)b * (HIN * WIN * CVEC);
    size_t r0 = bbase + (size_t)y0 * (WIN * CVEC);
    size_t r1 = bbase + (size_t)y1 * (WIN * CVEC);
    size_t ca = (size_t)x0 * CVEC + g;
    size_t cc = (size_t)x1 * CVEC + g;

    float4 pa = __ldg(Xv + r0 + ca);
    float4 pb = __ldg(Xv + r1 + ca);
    float4 pc = __ldg(Xv + r0 + cc);
    float4 pd = __ldg(Xv + r1 + cc);

    float4 o;
    o.x = wa * pa.x + wb * pb.x + wc * pc.x + wd * pd.x;
    o.y = wa * pa.y + wb * pb.y + wc * pc.y + wd * pd.y;
    o.z = wa * pa.z + wb * pb.z + wc * pc.z + wd * pd.z;
    o.w = wa * pa.w + wb * pb.w + wc * pc.w + wd * pd.w;

    ((float4*)out)[(size_t)p * CVEC + g] = o;
}

extern "C" void kernel_launch(void* const* d_in, const int* in_sizes, int n_in,
                              void* d_out, int out_size)
{
    const float* X = (const float*)d_in[0];
    const float* T = (const float*)d_in[1];
    float* out = (float*)d_out;

    const int total = 16 * OUT_H * OUT_W * CVEC;  // 12,845,056 threads
    const int threads = 128;
    const int blocks = total / threads;
    bilerp_kernel<<<blocks, threads>>>(X, T, out);
}